// round 4
// baseline (speedup 1.0000x reference)
#include <cuda_runtime.h>
#include <cuda_bf16.h>
#include <math_constants.h>
#include <cstdint>

#define N_ROWS 32768
#define D_DIM  256
#define K_CODES 1024
#define MARGIN 6.0e-3f

__device__ float  g_a[N_ROWS];
__device__ float  g_b[K_CODES];
__device__ int    g_idx[N_ROWS];
__device__ double g_part[64];
__device__ __align__(16) __nv_bfloat16 g_eb[K_CODES * D_DIM];

__device__ __forceinline__ uint32_t s2u(const void* p) {
    uint32_t a;
    asm("{ .reg .u64 t; cvta.to.shared.u64 t, %1; cvt.u32.u64 %0, t; }" : "=r"(a) : "l"(p));
    return a;
}
__device__ __forceinline__ uint32_t pbf2(float lo, float hi) {
    uint32_t r;
    asm("{.reg .b16 l,h;\n\tcvt.rn.bf16.f32 l,%1;\n\tcvt.rn.bf16.f32 h,%2;\n\tmov.b32 %0,{l,h};}"
        : "=r"(r) : "f"(lo), "f"(hi));
    return r;
}
__device__ __forceinline__ uint32_t fmap(float f) {
    uint32_t b = __float_as_uint(f);
    return b ^ ((b & 0x80000000u) ? 0xFFFFFFFFu : 0x80000000u);
}
__device__ __forceinline__ float funmap(uint32_t u) {
    uint32_t b = (u & 0x80000000u) ? (u ^ 0x80000000u) : ~u;
    return __uint_as_float(b);
}
#define LDSM4(d, addr) \
    asm volatile("ldmatrix.sync.aligned.m8n8.x4.shared.b16 {%0,%1,%2,%3}, [%4];" \
        : "=r"((d)[0]), "=r"((d)[1]), "=r"((d)[2]), "=r"((d)[3]) : "r"(addr))
#define MMA16816(c, a, b0, b1) \
    asm volatile("mma.sync.aligned.m16n8k16.row.col.f32.bf16.bf16.f32 " \
        "{%0,%1,%2,%3}, {%4,%5,%6,%7}, {%8,%9}, {%0,%1,%2,%3};" \
        : "+f"((c)[0]), "+f"((c)[1]), "+f"((c)[2]), "+f"((c)[3]) \
        : "r"((a)[0]), "r"((a)[1]), "r"((a)[2]), "r"((a)[3]), "r"(b0), "r"(b1))

// smem offsets (bytes)
#define OFF_A     0         // 256 rows x 512B = 131072
#define OFF_B     131072    // 128 rows x 512B = 65536
#define OFF_SHB   196608    // float[128]
#define OFF_SMIN  197120    // uint[256]
#define OFF_LIMF  198144    // float[256]
#define OFF_SBEST 199168    // ull[256]
#define SMEM_SZ   201216

// ===== kernel 1: norms (bitwise identical to 525us version) + emb->bf16 =====
__global__ void prep_norms(const float* __restrict__ z, const float* __restrict__ emb) {
    int warp = (blockIdx.x * blockDim.x + threadIdx.x) >> 5;
    int lane = threadIdx.x & 31;
    if (blockIdx.x == 0 && threadIdx.x < 64) g_part[threadIdx.x] = 0.0;
    const float* src; float* dst; bool is_e = false; int er = 0;
    if (warp < N_ROWS) { src = z + (size_t)warp * D_DIM; dst = g_a + warp; }
    else if (warp < N_ROWS + K_CODES) { er = warp - N_ROWS; src = emb + (size_t)er * D_DIM; dst = g_b + er; is_e = true; }
    else return;
    float s = 0.f;
#pragma unroll
    for (int i = 0; i < D_DIM / 32; i++) {
        float v = src[lane + i * 32];
        s = __fmaf_rn(v, v, s);
        if (is_e) g_eb[er * D_DIM + lane + i * 32] = __float2bfloat16_rn(v);
    }
#pragma unroll
    for (int o = 16; o > 0; o >>= 1) s = __fadd_rn(s, __shfl_down_sync(0xffffffffu, s, o));
    if (lane == 0) *dst = s;
}

// exact fp32 rescore: identical op sequence to the rel_err=0 scalar kernel
__device__ __noinline__ void rescore(const float* __restrict__ z, const float* __restrict__ emb,
                                     int row, int k, float bval,
                                     unsigned long long* __restrict__ sbest) {
    const float* zr = z + (size_t)row * D_DIM;
    const float* er = emb + (size_t)k * D_DIM;
    float c = 0.f;
#pragma unroll 8
    for (int i = 0; i < D_DIM; i += 4) {
        float4 a = *reinterpret_cast<const float4*>(zr + i);
        float4 b = *reinterpret_cast<const float4*>(er + i);
        c = __fmaf_rn(a.x, b.x, c); c = __fmaf_rn(a.y, b.y, c);
        c = __fmaf_rn(a.z, b.z, c); c = __fmaf_rn(a.w, b.w, c);
    }
    float d = __fmaf_rn(-2.0f, c, __fadd_rn(g_a[row], bval));
    unsigned long long pk = ((unsigned long long)fmap(d) << 32) | (unsigned)k;
    atomicMin(sbest, pk);
}

// ===== kernel 2: two-pass bf16 mma.sync GEMM + margin rescore =====
__global__ __launch_bounds__(512, 1)
void gemm_mma(const float* __restrict__ z, const float* __restrict__ emb) {
    extern __shared__ __align__(16) char smem[];
    const uint32_t sbase = s2u(smem);
    const int tid = threadIdx.x;
    const int t = tid & 31;
    const int w = tid >> 5;
    const int warpm = w & 3;         // 4 m-warps: 64 rows each
    const int warpn = w >> 2;        // 4 n-warps: 32 codes each
    const int row0 = blockIdx.x * 256;

    float*  shb  = reinterpret_cast<float*>(smem + OFF_SHB);
    uint32_t* smin = reinterpret_cast<uint32_t*>(smem + OFF_SMIN);
    float*  limf = reinterpret_cast<float*>(smem + OFF_LIMF);
    unsigned long long* sbest = reinterpret_cast<unsigned long long*>(smem + OFF_SBEST);

    if (tid < 256) { smin[tid] = 0xFFFFFFFFu; sbest[tid] = ~0ull; }

    // ---- load A: 256 rows x 256 bf16, 512B pitch, unit swizzle u^(row&7) ----
    for (int i = tid; i < 256 * 32; i += 512) {
        int r = i >> 5, u = i & 31;
        const float4* s4 = reinterpret_cast<const float4*>(z + (size_t)(row0 + r) * D_DIM + u * 8);
        float4 f0 = s4[0], f1 = s4[1];
        uint4 v = { pbf2(f0.x, f0.y), pbf2(f0.z, f0.w), pbf2(f1.x, f1.y), pbf2(f1.z, f1.w) };
        *reinterpret_cast<uint4*>(smem + OFF_A + r * 512 + ((u ^ (r & 7)) << 4)) = v;
    }

    // ldmatrix address precompute
    const int t7 = t & 7;
    const int arow = t7 + ((t >> 3) & 1) * 8;     // row within m16 tile
    const int asel = (t >> 4) & 1;                // k-unit select for A
    const int brow = t7 + ((t >> 4) & 1) * 8;     // row within n16 group
    const int bsel = (t >> 3) & 1;                // k-unit select for B
    const uint32_t abase = sbase + OFF_A + (uint32_t)(warpm * 64 + arow) * 512;
    const uint32_t bbase = sbase + OFF_B + (uint32_t)(warpn * 32 + brow) * 512;
    const int n0 = warpn * 32;
    const int crow = t >> 2;                      // accum row within 8
    const int ccol = 2 * (t & 3);                 // accum col base

    for (int g = 0; g < 16; g++) {
        const int cidx = g & 7, pass = g >> 3;
        const int c0 = cidx * 128;

        if (g == 8 && tid < 256) limf[tid] = funmap(smin[tid]) + MARGIN;
        if (tid < 128) shb[tid] = g_b[c0 + tid];
        for (int i = tid; i < 128 * 32; i += 512) {   // B chunk: 128 codes x 256 bf16
            int r = i >> 5, u = i & 31;
            uint4 v = *reinterpret_cast<const uint4*>(&g_eb[(c0 + r) * D_DIM + u * 8]);
            *reinterpret_cast<uint4*>(smem + OFF_B + r * 512 + ((u ^ (r & 7)) << 4)) = v;
        }
        __syncthreads();

        float c[4][4][4];
#pragma unroll
        for (int im = 0; im < 4; im++)
#pragma unroll
            for (int in = 0; in < 4; in++)
#pragma unroll
                for (int r = 0; r < 4; r++) c[im][in][r] = 0.f;

#pragma unroll
        for (int ks = 0; ks < 16; ks++) {
            uint32_t ua = (uint32_t)(((2 * ks + asel) ^ t7) << 4);
            uint32_t ub = (uint32_t)(((2 * ks + bsel) ^ t7) << 4);
            uint32_t af[4][4], bf[2][4];
#pragma unroll
            for (int im = 0; im < 4; im++) LDSM4(af[im], abase + im * 8192 + ua);
#pragma unroll
            for (int g2 = 0; g2 < 2; g2++) LDSM4(bf[g2], bbase + g2 * 8192 + ub);
#pragma unroll
            for (int im = 0; im < 4; im++) {
                MMA16816(c[im][0], af[im], bf[0][0], bf[0][1]);
                MMA16816(c[im][1], af[im], bf[0][2], bf[0][3]);
                MMA16816(c[im][2], af[im], bf[1][0], bf[1][1]);
                MMA16816(c[im][3], af[im], bf[1][2], bf[1][3]);
            }
        }

        // ---- epilogue ----
        if (pass == 0) {
#pragma unroll
            for (int im = 0; im < 4; im++) {
#pragma unroll
                for (int h = 0; h < 2; h++) {
                    float mn = CUDART_INF_F;
#pragma unroll
                    for (int in = 0; in < 4; in++) {
                        int nl = n0 + in * 8 + ccol;
                        mn = fminf(mn, __fmaf_rn(-2.0f, c[im][in][2 * h],     shb[nl]));
                        mn = fminf(mn, __fmaf_rn(-2.0f, c[im][in][2 * h + 1], shb[nl + 1]));
                    }
                    mn = fminf(mn, __shfl_xor_sync(0xffffffffu, mn, 1));
                    mn = fminf(mn, __shfl_xor_sync(0xffffffffu, mn, 2));
                    if ((t & 3) == 0) {
                        int row = warpm * 64 + im * 16 + crow + h * 8;
                        atomicMin(&smin[row], fmap(mn));
                    }
                }
            }
        } else {
#pragma unroll
            for (int im = 0; im < 4; im++) {
#pragma unroll
                for (int h = 0; h < 2; h++) {
                    int row = warpm * 64 + im * 16 + crow + h * 8;
                    float lim = limf[row];
#pragma unroll
                    for (int in = 0; in < 4; in++) {
#pragma unroll
                        for (int p = 0; p < 2; p++) {
                            int nl = n0 + in * 8 + ccol + p;
                            float s = __fmaf_rn(-2.0f, c[im][in][2 * h + p], shb[nl]);
                            if (s <= lim)
                                rescore(z, emb, row0 + row, c0 + nl, shb[nl], &sbest[row]);
                        }
                    }
                }
            }
        }
        __syncthreads();
    }

    if (tid < 256) g_idx[row0 + tid] = (int)(unsigned)(sbest[tid] & 0xFFFFFFFFull);
}

// ===== kernel 3: gather + straight-through output + MSE partials =====
__global__ void finalize_out(const float* __restrict__ z, const float* __restrict__ emb,
                             float* __restrict__ out) {
    int tt = blockIdx.x * 256 + threadIdx.x;
    int base = tt * 4, n = base >> 8, d0 = base & 255;
    int code = g_idx[n];
    float4 q  = *reinterpret_cast<const float4*>(&emb[(size_t)code * D_DIM + d0]);
    float4 zv = *reinterpret_cast<const float4*>(&z[(size_t)base]);
    float dx = __fadd_rn(q.x, -zv.x), dy = __fadd_rn(q.y, -zv.y);
    float dz = __fadd_rn(q.z, -zv.z), dw = __fadd_rn(q.w, -zv.w);
    float4 ov = { __fadd_rn(zv.x, dx), __fadd_rn(zv.y, dy), __fadd_rn(zv.z, dz), __fadd_rn(zv.w, dw) };
    *reinterpret_cast<float4*>(&out[(size_t)base]) = ov;

    double s = (double)dx * dx + (double)dy * dy + (double)dz * dz + (double)dw * dw;
#pragma unroll
    for (int o = 16; o > 0; o >>= 1) s += __shfl_down_sync(0xffffffffu, s, o);
    __shared__ double ws[8];
    int lane = threadIdx.x & 31, wid = threadIdx.x >> 5;
    if (lane == 0) ws[wid] = s;
    __syncthreads();
    if (threadIdx.x == 0) {
        double bs = 0.0;
#pragma unroll
        for (int ww = 0; ww < 8; ww++) bs += ws[ww];
        atomicAdd(&g_part[blockIdx.x & 63], bs);
    }
}

__global__ void loss_final(float* __restrict__ out, int out_size) {
    if (threadIdx.x == 0 && blockIdx.x == 0) {
        double s = 0.0;
        for (int i = 0; i < 64; i++) s += g_part[i];
        float mf = (float)(s / (double)((size_t)N_ROWS * D_DIM));
        out[out_size - 1] = __fadd_rn(mf, __fmul_rn(0.25f, mf));
    }
}

extern "C" void kernel_launch(void* const* d_in, const int* in_sizes, int n_in,
                              void* d_out, int out_size) {
    const float* z   = (const float*)d_in[0];
    const float* emb = (const float*)d_in[1];
    float* out = (float*)d_out;

    cudaFuncSetAttribute(gemm_mma, cudaFuncAttributeMaxDynamicSharedMemorySize, SMEM_SZ);

    prep_norms<<<(N_ROWS + K_CODES) / 8, 256>>>(z, emb);
    gemm_mma<<<N_ROWS / 256, 512, SMEM_SZ>>>(z, emb);
    finalize_out<<<(N_ROWS * D_DIM) / (256 * 4), 256>>>(z, emb, out);
    loss_final<<<1, 32>>>(out, out_size);
}

// round 5
// speedup vs baseline: 2.0131x; 2.0131x over previous
#include <cuda_runtime.h>
#include <cuda_bf16.h>
#include <math_constants.h>
#include <cstdint>

#define N_ROWS 32768
#define D_DIM  256
#define K_CODES 1024
#define MARGIN 6.0e-3f
#define CAP 28

__device__ float  g_a[N_ROWS];
__device__ float  g_b[K_CODES];
__device__ int    g_idx[N_ROWS];
__device__ double g_part[64];
__device__ __align__(16) __nv_bfloat16 g_eb[K_CODES * D_DIM];

__device__ __forceinline__ uint32_t s2u(const void* p) {
    uint32_t a;
    asm("{ .reg .u64 t; cvta.to.shared.u64 t, %1; cvt.u32.u64 %0, t; }" : "=r"(a) : "l"(p));
    return a;
}
__device__ __forceinline__ uint32_t pbf2(float lo, float hi) {
    uint32_t r;
    asm("{.reg .b16 l,h;\n\tcvt.rn.bf16.f32 l,%1;\n\tcvt.rn.bf16.f32 h,%2;\n\tmov.b32 %0,{l,h};}"
        : "=r"(r) : "f"(lo), "f"(hi));
    return r;
}
__device__ __forceinline__ uint32_t fmap(float f) {
    uint32_t b = __float_as_uint(f);
    return b ^ ((b & 0x80000000u) ? 0xFFFFFFFFu : 0x80000000u);
}
__device__ __forceinline__ float funmap(uint32_t u) {
    uint32_t b = (u & 0x80000000u) ? (u ^ 0x80000000u) : ~u;
    return __uint_as_float(b);
}
#define LDSM4(d, addr) \
    asm volatile("ldmatrix.sync.aligned.m8n8.x4.shared.b16 {%0,%1,%2,%3}, [%4];" \
        : "=r"((d)[0]), "=r"((d)[1]), "=r"((d)[2]), "=r"((d)[3]) : "r"(addr))
#define MMA16816(c, a, b0, b1) \
    asm volatile("mma.sync.aligned.m16n8k16.row.col.f32.bf16.bf16.f32 " \
        "{%0,%1,%2,%3}, {%4,%5,%6,%7}, {%8,%9}, {%0,%1,%2,%3};" \
        : "+f"((c)[0]), "+f"((c)[1]), "+f"((c)[2]), "+f"((c)[3]) \
        : "r"((a)[0]), "r"((a)[1]), "r"((a)[2]), "r"((a)[3]), "r"(b0), "r"(b1))
#define CP16(dst, src) \
    asm volatile("cp.async.cg.shared.global [%0], [%1], 16;" :: "r"(dst), "l"(src) : "memory")
#define CP_COMMIT() asm volatile("cp.async.commit_group;" ::: "memory")
#define CP_WAIT0()  asm volatile("cp.async.wait_group 0;" ::: "memory")

// smem layout (bytes)
#define OFF_A     0        // 128 rows x 512B = 65536
#define OFF_B     65536    // 2 bufs x 128 x 512B = 131072
#define OFF_SHB   196608   // float[2][128] = 1024
#define OFF_SMIN  197632   // uint[128]
#define OFF_CNT   198144   // int[128]
#define OFF_LIMF  198656   // float[128]
#define OFF_SBEST 199168   // ull[128] = 1024
#define OFF_CAND  200192   // ull[128*CAP] = 28672
#define SMEM_SZ   228864

// ===== kernel 1: norms (bitwise identical to 525us version) + emb->bf16 =====
__global__ void prep_norms(const float* __restrict__ z, const float* __restrict__ emb) {
    int warp = (blockIdx.x * blockDim.x + threadIdx.x) >> 5;
    int lane = threadIdx.x & 31;
    if (blockIdx.x == 0 && threadIdx.x < 64) g_part[threadIdx.x] = 0.0;
    const float* src; float* dst; bool is_e = false; int er = 0;
    if (warp < N_ROWS) { src = z + (size_t)warp * D_DIM; dst = g_a + warp; }
    else if (warp < N_ROWS + K_CODES) { er = warp - N_ROWS; src = emb + (size_t)er * D_DIM; dst = g_b + er; is_e = true; }
    else return;
    float s = 0.f;
#pragma unroll
    for (int i = 0; i < D_DIM / 32; i++) {
        float v = src[lane + i * 32];
        s = __fmaf_rn(v, v, s);
        if (is_e) g_eb[er * D_DIM + lane + i * 32] = __float2bfloat16_rn(v);
    }
#pragma unroll
    for (int o = 16; o > 0; o >>= 1) s = __fadd_rn(s, __shfl_down_sync(0xffffffffu, s, o));
    if (lane == 0) *dst = s;
}

// exact fp32 rescore: identical op sequence to the rel_err=0 scalar kernel
__device__ __noinline__ void rescore(const float* __restrict__ z, const float* __restrict__ emb,
                                     int row, int k,
                                     unsigned long long* __restrict__ sbest) {
    const float* zr = z + (size_t)row * D_DIM;
    const float* er = emb + (size_t)k * D_DIM;
    float c = 0.f;
#pragma unroll 8
    for (int i = 0; i < D_DIM; i += 4) {
        float4 a = *reinterpret_cast<const float4*>(zr + i);
        float4 b = *reinterpret_cast<const float4*>(er + i);
        c = __fmaf_rn(a.x, b.x, c); c = __fmaf_rn(a.y, b.y, c);
        c = __fmaf_rn(a.z, b.z, c); c = __fmaf_rn(a.w, b.w, c);
    }
    float d = __fmaf_rn(-2.0f, c, __fadd_rn(g_a[row], g_b[k]));
    unsigned long long pk = ((unsigned long long)fmap(d) << 32) | (unsigned)k;
    atomicMin(sbest, pk);
}

// ===== kernel 2: single-pass bf16 mma.sync GEMM + candidate lists + exact rescore =====
__global__ __launch_bounds__(256, 1)
void gemm_mma(const float* __restrict__ z, const float* __restrict__ emb) {
    extern __shared__ __align__(16) char smem[];
    const uint32_t sbase = s2u(smem);
    const int tid = threadIdx.x;
    const int t = tid & 31;
    const int w = tid >> 5;
    const int warpm = w & 1;          // 2 m-warps: 64 rows each
    const int warpn = w >> 1;         // 4 n-warps: 32 codes each
    const int row0 = blockIdx.x * 128;

    float (*shb)[128] = reinterpret_cast<float (*)[128]>(smem + OFF_SHB);
    uint32_t* smin = reinterpret_cast<uint32_t*>(smem + OFF_SMIN);
    int*      cnt  = reinterpret_cast<int*>(smem + OFF_CNT);
    float*    limf = reinterpret_cast<float*>(smem + OFF_LIMF);
    unsigned long long* sbest = reinterpret_cast<unsigned long long*>(smem + OFF_SBEST);
    unsigned long long* cand  = reinterpret_cast<unsigned long long*>(smem + OFF_CAND);

    if (tid < 128) {
        smin[tid] = 0xFF800000u;     // fmap(+inf)
        cnt[tid] = 0;
        sbest[tid] = ~0ull;
        shb[0][tid] = g_b[tid];
    }

    // prologue: cp.async B chunk 0 into buf 0
    for (int i = tid; i < 128 * 32; i += 256) {
        int r = i >> 5, u = i & 31;
        CP16(sbase + OFF_B + r * 512 + ((u ^ (r & 7)) << 4),
             (const void*)&g_eb[r * D_DIM + u * 8]);
    }
    CP_COMMIT();

    // A: 128 rows x 256 bf16 (fp32 -> bf16 convert), 512B pitch, unit swizzle
    for (int i = tid; i < 128 * 32; i += 256) {
        int r = i >> 5, u = i & 31;
        const float4* s4 = reinterpret_cast<const float4*>(z + (size_t)(row0 + r) * D_DIM + u * 8);
        float4 f0 = s4[0], f1 = s4[1];
        uint4 v = { pbf2(f0.x, f0.y), pbf2(f0.z, f0.w), pbf2(f1.x, f1.y), pbf2(f1.z, f1.w) };
        *reinterpret_cast<uint4*>(smem + OFF_A + r * 512 + ((u ^ (r & 7)) << 4)) = v;
    }
    CP_WAIT0();
    __syncthreads();

    // ldmatrix address precompute
    const int t7 = t & 7;
    const int arow = t7 + ((t >> 3) & 1) * 8;
    const int asel = (t >> 4) & 1;
    const int brow = t7 + ((t >> 4) & 1) * 8;
    const int bsel = (t >> 3) & 1;
    const uint32_t abase = sbase + OFF_A + (uint32_t)(warpm * 64 + arow) * 512;
    const int n0 = warpn * 32;
    const int crow = t >> 2;
    const int ccol = 2 * (t & 3);

    for (int c = 0; c < 8; c++) {
        const int b = c & 1;
        const int c0 = c * 128;
        const uint32_t bbase = sbase + OFF_B + (uint32_t)(b * 65536 + (warpn * 32 + brow) * 512);

        // prefetch next B chunk into buf b^1
        if (c < 7) {
            if (tid < 128) shb[b ^ 1][tid] = g_b[c0 + 128 + tid];
            for (int i = tid; i < 128 * 32; i += 256) {
                int r = i >> 5, u = i & 31;
                CP16(sbase + OFF_B + (b ^ 1) * 65536 + r * 512 + ((u ^ (r & 7)) << 4),
                     (const void*)&g_eb[(c0 + 128 + r) * D_DIM + u * 8]);
            }
            CP_COMMIT();
        }

        float acc[4][4][4];
#pragma unroll
        for (int im = 0; im < 4; im++)
#pragma unroll
            for (int in = 0; in < 4; in++)
#pragma unroll
                for (int r = 0; r < 4; r++) acc[im][in][r] = 0.f;

#pragma unroll
        for (int ks = 0; ks < 16; ks++) {
            uint32_t ua = (uint32_t)(((2 * ks + asel) ^ t7) << 4);
            uint32_t ub = (uint32_t)(((2 * ks + bsel) ^ t7) << 4);
            uint32_t af[4][4], bf[2][4];
#pragma unroll
            for (int im = 0; im < 4; im++) LDSM4(af[im], abase + im * 8192 + ua);
#pragma unroll
            for (int g2 = 0; g2 < 2; g2++) LDSM4(bf[g2], bbase + g2 * 8192 + ub);
#pragma unroll
            for (int im = 0; im < 4; im++) {
                MMA16816(acc[im][0], af[im], bf[0][0], bf[0][1]);
                MMA16816(acc[im][1], af[im], bf[0][2], bf[0][3]);
                MMA16816(acc[im][2], af[im], bf[1][0], bf[1][1]);
                MMA16816(acc[im][3], af[im], bf[1][2], bf[1][3]);
            }
        }

        // ---- epilogue: running min + candidate collection ----
#pragma unroll
        for (int im = 0; im < 4; im++) {
#pragma unroll
            for (int h = 0; h < 2; h++) {
                const int row = warpm * 64 + im * 16 + crow + h * 8;
                float se[8];
                float mn = CUDART_INF_F;
#pragma unroll
                for (int in = 0; in < 4; in++) {
                    int nl = n0 + in * 8 + ccol;
                    float s0 = __fmaf_rn(-2.0f, acc[im][in][2 * h],     shb[b][nl]);
                    float s1 = __fmaf_rn(-2.0f, acc[im][in][2 * h + 1], shb[b][nl + 1]);
                    se[2 * in] = s0; se[2 * in + 1] = s1;
                    mn = fminf(mn, fminf(s0, s1));
                }
                mn = fminf(mn, __shfl_xor_sync(0xffffffffu, mn, 1));
                mn = fminf(mn, __shfl_xor_sync(0xffffffffu, mn, 2));
                if ((t & 3) == 0) atomicMin(&smin[row], fmap(mn));
                float lim = fminf(funmap(smin[row]), mn) + MARGIN;
#pragma unroll
                for (int e = 0; e < 8; e++) {
                    if (se[e] <= lim) {
                        int k = c0 + n0 + (e >> 1) * 8 + ccol + (e & 1);
                        int idx = atomicAdd(&cnt[row], 1);
                        if (idx < CAP)
                            cand[row * CAP + idx] =
                                ((unsigned long long)__float_as_uint(se[e]) << 32) | (unsigned)k;
                    }
                }
            }
        }
        if (c < 7) CP_WAIT0();
        __syncthreads();
    }

    // ---- final limits ----
    if (tid < 128) limf[tid] = funmap(smin[tid]) + MARGIN;
    __syncthreads();

    // ---- filter candidates + exact rescore ----
    for (int i = tid; i < 128 * CAP; i += 256) {
        int row = i / CAP, slot = i % CAP;
        int ne = min(cnt[row], CAP);
        if (slot < ne) {
            unsigned long long pk = cand[row * CAP + slot];
            float s = __uint_as_float((uint32_t)(pk >> 32));
            if (s <= limf[row])
                rescore(z, emb, row0 + row, (int)(unsigned)(pk & 0xFFFFFFFFull), &sbest[row]);
        }
    }
    // overflow fallback (essentially never taken; guarantees correctness)
    for (int row = w; row < 128; row += 8) {
        if (cnt[row] > CAP)
            for (int k = t; k < K_CODES; k += 32)
                rescore(z, emb, row0 + row, k, &sbest[row]);
    }
    __syncthreads();

    if (tid < 128) g_idx[row0 + tid] = (int)(unsigned)(sbest[tid] & 0xFFFFFFFFull);
}

// ===== kernel 3: gather + straight-through output + MSE partials =====
__global__ void finalize_out(const float* __restrict__ z, const float* __restrict__ emb,
                             float* __restrict__ out) {
    int tt = blockIdx.x * 256 + threadIdx.x;
    int base = tt * 4, n = base >> 8, d0 = base & 255;
    int code = g_idx[n];
    float4 q  = *reinterpret_cast<const float4*>(&emb[(size_t)code * D_DIM + d0]);
    float4 zv = *reinterpret_cast<const float4*>(&z[(size_t)base]);
    float dx = __fadd_rn(q.x, -zv.x), dy = __fadd_rn(q.y, -zv.y);
    float dz = __fadd_rn(q.z, -zv.z), dw = __fadd_rn(q.w, -zv.w);
    float4 ov = { __fadd_rn(zv.x, dx), __fadd_rn(zv.y, dy), __fadd_rn(zv.z, dz), __fadd_rn(zv.w, dw) };
    *reinterpret_cast<float4*>(&out[(size_t)base]) = ov;

    double s = (double)dx * dx + (double)dy * dy + (double)dz * dz + (double)dw * dw;
#pragma unroll
    for (int o = 16; o > 0; o >>= 1) s += __shfl_down_sync(0xffffffffu, s, o);
    __shared__ double ws[8];
    int lane = threadIdx.x & 31, wid = threadIdx.x >> 5;
    if (lane == 0) ws[wid] = s;
    __syncthreads();
    if (threadIdx.x == 0) {
        double bs = 0.0;
#pragma unroll
        for (int ww = 0; ww < 8; ww++) bs += ws[ww];
        atomicAdd(&g_part[blockIdx.x & 63], bs);
    }
}

__global__ void loss_final(float* __restrict__ out, int out_size) {
    if (threadIdx.x == 0 && blockIdx.x == 0) {
        double s = 0.0;
        for (int i = 0; i < 64; i++) s += g_part[i];
        float mf = (float)(s / (double)((size_t)N_ROWS * D_DIM));
        out[out_size - 1] = __fadd_rn(mf, __fmul_rn(0.25f, mf));
    }
}

extern "C" void kernel_launch(void* const* d_in, const int* in_sizes, int n_in,
                              void* d_out, int out_size) {
    const float* z   = (const float*)d_in[0];
    const float* emb = (const float*)d_in[1];
    float* out = (float*)d_out;

    cudaFuncSetAttribute(gemm_mma, cudaFuncAttributeMaxDynamicSharedMemorySize, SMEM_SZ);

    prep_norms<<<(N_ROWS + K_CODES) / 8, 256>>>(z, emb);
    gemm_mma<<<N_ROWS / 128, 256, SMEM_SZ>>>(z, emb);
    finalize_out<<<(N_ROWS * D_DIM) / (256 * 4), 256>>>(z, emb, out);
    loss_final<<<1, 32>>>(out, out_size);
}